// round 14
// baseline (speedup 1.0000x reference)
#include <cuda_runtime.h>
#include <cuda_bf16.h>
#include <stdint.h>

#define NN 100000
#define DD 128
#define EE 1600000
#define SCAN_B 98   // ceil(NN/1024)

// ---------------- scratch (device globals: no allocation allowed) ----------
__device__ __align__(16) float g_Y[(size_t)NN*DD];   // pre-BN linear output
__device__ __align__(16) float g_H[(size_t)NN*DD];   // post-activation features
__device__ __align__(16) float g_PS[(size_t)NN*32];  // layer3: [P(16) | S(16)]
__device__ __align__(16) __nv_bfloat16 g_Mh[(size_t)NN*DD];  // mean hi
__device__ __align__(16) __nv_bfloat16 g_Ml[(size_t)NN*DD];  // mean lo
__device__ __align__(16) __nv_bfloat16 g_Xh[(size_t)NN*DD];  // x hi
__device__ __align__(16) __nv_bfloat16 g_Xl[(size_t)NN*DD];  // x lo
__device__ __align__(16) __nv_bfloat16 g_Hh[(size_t)NN*DD];  // h hi
__device__ __align__(16) __nv_bfloat16 g_Hl[(size_t)NN*DD];  // h lo
__device__ __align__(16) __nv_bfloat16 g_Wt1[128*768];       // layer1 weights, [n][k]
__device__ __align__(16) __nv_bfloat16 g_Wt2[128*768];       // layer2 weights, [n][k]
__device__ int g_deg[NN];
__device__ int g_rowptr[NN+1];
__device__ int g_cursor[NN];
__device__ int g_csrsrc[EE];
__device__ int g_bsum[SCAN_B];
__device__ int g_boff[SCAN_B];
__device__ __align__(16) float g_colsum[2][DD];
__device__ __align__(16) float g_colsq[2][DD];
__device__ __align__(16) float g_scale[DD];
__device__ __align__(16) float g_shift[DD];
__device__ uint2 g_keys[2];

// ---------------- threefry2x32 (matches JAX) ------------------------------
__device__ __forceinline__ uint32_t rotl32(uint32_t v, int d) {
    return (v << d) | (v >> (32 - d));
}

__device__ __forceinline__ uint2 threefry(uint32_t k0, uint32_t k1,
                                          uint32_t x0, uint32_t x1) {
    uint32_t k2 = k0 ^ k1 ^ 0x1BD11BDAu;
    x0 += k0; x1 += k1;
#define TFR(a,b,c,d) \
    x0+=x1; x1=rotl32(x1,a); x1^=x0; \
    x0+=x1; x1=rotl32(x1,b); x1^=x0; \
    x0+=x1; x1=rotl32(x1,c); x1^=x0; \
    x0+=x1; x1=rotl32(x1,d); x1^=x0;
    TFR(13,15,26,6)   x0+=k1; x1+=k2+1u;
    TFR(17,29,16,24)  x0+=k2; x1+=k0+2u;
    TFR(13,15,26,6)   x0+=k0; x1+=k1+3u;
    TFR(17,29,16,24)  x0+=k1; x1+=k2+4u;
    TFR(13,15,26,6)   x0+=k2; x1+=k0+5u;
#undef TFR
    return make_uint2(x0, x1);
}

// ---------------- fused init: zero deg, keys, zero both stat buffers -------
__global__ void k_init() {
    int i = blockIdx.x * blockDim.x + threadIdx.x;
    if (i < NN) g_deg[i] = 0;
    if (blockIdx.x == 0) {
        if (threadIdx.x == 0) {
            g_keys[0] = threefry(0u, 42u, 0u, 0u);
            g_keys[1] = threefry(0u, 42u, 0u, 1u);
        }
        if (threadIdx.x < 128) {
            g_colsum[0][threadIdx.x] = 0.f; g_colsq[0][threadIdx.x] = 0.f;
            g_colsum[1][threadIdx.x] = 0.f; g_colsq[1][threadIdx.x] = 0.f;
        }
    }
}

// ---------------- CSR build ------------------------------------------------
__global__ void k_deg(const int* __restrict__ dst) {
    int e = blockIdx.x * blockDim.x + threadIdx.x;
    if (e < EE) atomicAdd(&g_deg[dst[e]], 1);
}

__global__ void k_scan1() {
    __shared__ int sh[1024];
    int tid = threadIdx.x;
    int i = blockIdx.x * 1024 + tid;
    int v = (i < NN) ? g_deg[i] : 0;
    sh[tid] = v;
    __syncthreads();
    for (int off = 1; off < 1024; off <<= 1) {
        int t = (tid >= off) ? sh[tid - off] : 0;
        __syncthreads();
        sh[tid] += t;
        __syncthreads();
    }
    if (i < NN) g_rowptr[i] = sh[tid] - v;
    if (tid == 1023) g_bsum[blockIdx.x] = sh[1023];
}

__global__ void k_scan2() {
    __shared__ int sh[128];
    int tid = threadIdx.x;
    int v = (tid < SCAN_B) ? g_bsum[tid] : 0;
    sh[tid] = v;
    __syncthreads();
    for (int off = 1; off < 128; off <<= 1) {
        int t = (tid >= off) ? sh[tid - off] : 0;
        __syncthreads();
        sh[tid] += t;
        __syncthreads();
    }
    if (tid < SCAN_B) g_boff[tid] = sh[tid] - v;
    if (tid == 127) g_rowptr[NN] = sh[127];
}

__global__ void k_scan3() {
    int i = blockIdx.x * blockDim.x + threadIdx.x;
    if (i < NN) {
        int r = g_rowptr[i] + g_boff[i >> 10];
        g_rowptr[i] = r;
        g_cursor[i] = r;
    }
}

__global__ void k_fill(const int* __restrict__ src, const int* __restrict__ dst) {
    int e = blockIdx.x * blockDim.x + threadIdx.x;
    if (e < EE) {
        int p = atomicAdd(&g_cursor[dst[e]], 1);
        g_csrsrc[p] = src[e];
    }
}

// ---------------- mean aggregation (warp per node) → bf16 hi/lo -----------
__global__ void k_agg(const float* __restrict__ X) {
    int w = (blockIdx.x * blockDim.x + threadIdx.x) >> 5;
    int lane = threadIdx.x & 31;
    if (w >= NN) return;
    int s0 = g_rowptr[w], s1 = g_rowptr[w + 1];
    float4 acc = make_float4(0.f, 0.f, 0.f, 0.f);
    int e = s0;
    for (; e + 4 <= s1; e += 4) {
        int a = g_csrsrc[e], b = g_csrsrc[e+1], c = g_csrsrc[e+2], d = g_csrsrc[e+3];
        float4 va = *(const float4*)(X + (size_t)a * DD + lane * 4);
        float4 vb = *(const float4*)(X + (size_t)b * DD + lane * 4);
        float4 vc = *(const float4*)(X + (size_t)c * DD + lane * 4);
        float4 vd = *(const float4*)(X + (size_t)d * DD + lane * 4);
        acc.x += va.x + vb.x + vc.x + vd.x;
        acc.y += va.y + vb.y + vc.y + vd.y;
        acc.z += va.z + vb.z + vc.z + vd.z;
        acc.w += va.w + vb.w + vc.w + vd.w;
    }
    for (; e < s1; e++) {
        int a = g_csrsrc[e];
        float4 va = *(const float4*)(X + (size_t)a * DD + lane * 4);
        acc.x += va.x; acc.y += va.y; acc.z += va.z; acc.w += va.w;
    }
    float inv = 1.f / fmaxf((float)(s1 - s0), 1.f);
    float m[4] = {acc.x * inv, acc.y * inv, acc.z * inv, acc.w * inv};
    size_t base = (size_t)w * DD + lane * 4;
#pragma unroll
    for (int j = 0; j < 4; j++) {
        __nv_bfloat16 h = __float2bfloat16(m[j]);
        __nv_bfloat16 l = __float2bfloat16(m[j] - __bfloat162float(h));
        g_Mh[base + j] = h;
        g_Ml[base + j] = l;
    }
}

// ---------------- split x into bf16 hi/lo ----------------------------------
__global__ void k_cvt_x(const float* __restrict__ X) {
    int t = blockIdx.x * blockDim.x + threadIdx.x;
    size_t base = (size_t)t * 4;
    if (base >= (size_t)NN * DD) return;
    float4 v = *(const float4*)(X + base);
    float m[4] = {v.x, v.y, v.z, v.w};
#pragma unroll
    for (int j = 0; j < 4; j++) {
        __nv_bfloat16 h = __float2bfloat16(m[j]);
        __nv_bfloat16 l = __float2bfloat16(m[j] - __bfloat162float(h));
        g_Xh[base + j] = h;
        g_Xl[base + j] = l;
    }
}

// ---------------- build transposed split weights Wt[n][768] ----------------
// logical K rows: [Wl_h | Wl_l | Wl_h | Wr_h | Wr_l | Wr_h]
__global__ void k_cvt_w(const float* __restrict__ Wl, const float* __restrict__ Wr,
                        __nv_bfloat16* __restrict__ Wt) {
    int idx = blockIdx.x * blockDim.x + threadIdx.x;   // 0..98303
    if (idx >= 768 * 128) return;
    int n = idx & 127;
    int rr = idx >> 7;          // 0..767
    int seg = rr >> 7, kk = rr & 127;
    const float* src = (seg < 3) ? Wl : Wr;
    float w = src[kk * 128 + n];
    __nv_bfloat16 h = __float2bfloat16(w);
    __nv_bfloat16 l = __float2bfloat16(w - __bfloat162float(h));
    bool lopart = (seg == 1 || seg == 4);
    Wt[(size_t)n * 768 + rr] = lopart ? l : h;
}

// ================= helpers ================================================
__device__ __forceinline__ uint32_t s2u(const void* p) {
    uint32_t a;
    asm("{ .reg .u64 t; cvta.to.shared.u64 t, %1; cvt.u32.u64 %0, t; }"
        : "=r"(a) : "l"(p));
    return a;
}

__device__ __forceinline__ void cp_async16(uint32_t saddr, const void* gaddr, int sz) {
    asm volatile("cp.async.cg.shared.global [%0], [%1], 16, %2;"
                 :: "r"(saddr), "l"(gaddr), "r"(sz));
}

__device__ __forceinline__ void ldsm_x4(uint32_t* r, uint32_t addr) {
    asm volatile("ldmatrix.sync.aligned.m8n8.x4.shared.b16 {%0,%1,%2,%3}, [%4];"
                 : "=r"(r[0]), "=r"(r[1]), "=r"(r[2]), "=r"(r[3]) : "r"(addr));
}

// smem: 3 stages x (A 16KB + B 16KB) + aux
#define ST_BYTES 32768
#define SM_BIAS  98304
#define SM_RS    (98304 + 512)
#define SM_RQ    (98304 + 1024)
#define SM_TOT   (98304 + 1536)

// ---------------- HMMA GEMM: C[128r,128c] = A[128,768] @ Wt^T + bias -------
// 12 K-chunks of 64: A source = {Mh,Mh,Ml,Bh,Bh,Bl}[h>>1], col (h&1)*64
// 512 threads (16 warps, 4x4 grid, 32x32 warp tile), 2 CTAs/SM → 8 warps/SMSP
__global__ __launch_bounds__(512, 2)
void k_mma(const __nv_bfloat16* __restrict__ Ah,
           const __nv_bfloat16* __restrict__ Al,
           const __nv_bfloat16* __restrict__ Bh,
           const __nv_bfloat16* __restrict__ Bl,
           const __nv_bfloat16* __restrict__ Wt,
           const float* __restrict__ bias,
           float* __restrict__ C,
           float* __restrict__ colsum,
           float* __restrict__ colsq) {
    extern __shared__ __align__(128) char smem[];
    uint32_t su = s2u(smem);
    int tid  = threadIdx.x;
    int lane = tid & 31;
    int warp = tid >> 5;        // 0..15
    int wm = warp & 3;          // 4 warps over M (32 rows each)
    int wn = warp >> 2;         // 4 warps over N (32 cols each)
    int row0 = blockIdx.x * 128;

    float* biasS = (float*)(smem + SM_BIAS);
    float* redS  = (float*)(smem + SM_RS);
    float* redQ  = (float*)(smem + SM_RQ);
    if (tid < 128) { biasS[tid] = bias[tid]; redS[tid] = 0.f; redQ[tid] = 0.f; }

    // issue one stage's cp.async group (A tile + B tile, 128x64 bf16 each)
    auto issue = [&](int h) {
        int c = h >> 1;
        const __nv_bfloat16* Asrc =
            (c <= 1) ? Ah : (c == 2) ? Al : (c <= 4) ? Bh : Bl;
        int acol = (h & 1) * 64;
        uint32_t sa = su + (h % 3) * ST_BYTES;
        uint32_t sb = sa + 16384;
#pragma unroll
        for (int t = 0; t < 2; t++) {
            int q = tid + t * 512;          // 0..1023
            int r = q >> 3, g = q & 7;
            uint32_t off = (uint32_t)r * 128 + (((uint32_t)g << 4) ^ ((uint32_t)(r & 7) << 4));
            bool live = (row0 + r) < NN;
            const __nv_bfloat16* gA =
                Asrc + (live ? ((size_t)(row0 + r) * 128 + acol + g * 8) : 0);
            cp_async16(sa + off, gA, live ? 16 : 0);
            const __nv_bfloat16* gB = Wt + (size_t)r * 768 + h * 64 + g * 8;
            cp_async16(sb + off, gB, 16);
        }
        asm volatile("cp.async.commit_group;" ::: "memory");
    };

    issue(0);
    issue(1);

    float acc[2][4][4];
#pragma unroll
    for (int i = 0; i < 2; i++)
#pragma unroll
        for (int j = 0; j < 4; j++)
#pragma unroll
            for (int k = 0; k < 4; k++) acc[i][j][k] = 0.f;

    int sub = lane >> 3, ri = lane & 7;
    int rsel = ((sub & 1) << 3) + ri;      // row offset within 16-row frag
    int csel = (sub >> 1) << 4;            // 0 or 16 bytes (k half)

    for (int h = 0; h < 12; h++) {
        // final iteration: only its own group pending — drain fully
        if (h == 11)
            asm volatile("cp.async.wait_group 0;" ::: "memory");
        else
            asm volatile("cp.async.wait_group 1;" ::: "memory");
        __syncthreads();
        uint32_t sa = su + (h % 3) * ST_BYTES;
        uint32_t sb = sa + 16384;
#pragma unroll
        for (int ks = 0; ks < 4; ks++) {
            int kb = ks * 32;
            uint32_t af[2][4];
#pragma unroll
            for (int mt = 0; mt < 2; mt++) {
                int r = wm * 32 + mt * 16 + rsel;
                int bc = kb + csel;
                uint32_t ad = sa + (uint32_t)r * 128
                            + ((uint32_t)bc ^ ((uint32_t)ri << 4));
                ldsm_x4(af[mt], ad);
            }
            uint32_t bfr[4][2];
#pragma unroll
            for (int p = 0; p < 2; p++) {
                int r = wn * 32 + p * 16 + rsel;
                int bc = kb + csel;
                uint32_t ad = sb + (uint32_t)r * 128
                            + ((uint32_t)bc ^ ((uint32_t)ri << 4));
                uint32_t q[4];
                ldsm_x4(q, ad);
                bfr[2*p][0]   = q[0]; bfr[2*p][1]   = q[2];
                bfr[2*p+1][0] = q[1]; bfr[2*p+1][1] = q[3];
            }
#pragma unroll
            for (int mt = 0; mt < 2; mt++)
#pragma unroll
                for (int nt = 0; nt < 4; nt++) {
                    asm volatile(
                        "mma.sync.aligned.m16n8k16.row.col.f32.bf16.bf16.f32 "
                        "{%0,%1,%2,%3}, {%4,%5,%6,%7}, {%8,%9}, {%0,%1,%2,%3};"
                        : "+f"(acc[mt][nt][0]), "+f"(acc[mt][nt][1]),
                          "+f"(acc[mt][nt][2]), "+f"(acc[mt][nt][3])
                        : "r"(af[mt][0]), "r"(af[mt][1]),
                          "r"(af[mt][2]), "r"(af[mt][3]),
                          "r"(bfr[nt][0]), "r"(bfr[nt][1]));
                }
        }
        if (h + 2 < 12) issue(h + 2);
    }

    // ---- epilogue: bias, store, fused BN stats ----
    int g4 = lane >> 2, t4 = lane & 3;
    float bias2[4][2];
#pragma unroll
    for (int nt = 0; nt < 4; nt++) {
        int nc = wn * 32 + nt * 8 + 2 * t4;
        bias2[nt][0] = biasS[nc];
        bias2[nt][1] = biasS[nc + 1];
    }
    float cs[4][2], cq[4][2];
#pragma unroll
    for (int nt = 0; nt < 4; nt++) { cs[nt][0]=0.f; cs[nt][1]=0.f; cq[nt][0]=0.f; cq[nt][1]=0.f; }
#pragma unroll
    for (int mt = 0; mt < 2; mt++) {
        int r0 = row0 + wm * 32 + mt * 16 + g4;
        int r1 = r0 + 8;
#pragma unroll
        for (int nt = 0; nt < 4; nt++) {
            int nc = wn * 32 + nt * 8 + 2 * t4;
            if (r0 < NN) {
                float v0 = acc[mt][nt][0] + bias2[nt][0];
                float v1 = acc[mt][nt][1] + bias2[nt][1];
                *(float2*)(C + (size_t)r0 * 128 + nc) = make_float2(v0, v1);
                cs[nt][0] += v0; cq[nt][0] += v0 * v0;
                cs[nt][1] += v1; cq[nt][1] += v1 * v1;
            }
            if (r1 < NN) {
                float v2 = acc[mt][nt][2] + bias2[nt][0];
                float v3 = acc[mt][nt][3] + bias2[nt][1];
                *(float2*)(C + (size_t)r1 * 128 + nc) = make_float2(v2, v3);
                cs[nt][0] += v2; cq[nt][0] += v2 * v2;
                cs[nt][1] += v3; cq[nt][1] += v3 * v3;
            }
        }
    }
    __syncthreads();
#pragma unroll
    for (int nt = 0; nt < 4; nt++) {
        int nc = wn * 32 + nt * 8 + 2 * t4;
        atomicAdd(&redS[nc],     cs[nt][0]);
        atomicAdd(&redS[nc + 1], cs[nt][1]);
        atomicAdd(&redQ[nc],     cq[nt][0]);
        atomicAdd(&redQ[nc + 1], cq[nt][1]);
    }
    __syncthreads();
    if (tid < 128) {
        atomicAdd(&colsum[tid], redS[tid]);
        atomicAdd(&colsq[tid],  redQ[tid]);
    }
}

// ---------------- BN finalize ----------------------------------------------
__global__ void k_finalize(const float* __restrict__ gamma,
                           const float* __restrict__ beta, int layer) {
    int c = threadIdx.x;
    float mu  = g_colsum[layer][c] / (float)NN;
    float var = g_colsq[layer][c] / (float)NN - mu * mu;
    float r = rsqrtf(var + 1e-5f);
    float sc = gamma[c] * r;
    g_scale[c] = sc;
    g_shift[c] = beta[c] - mu * sc;
}

// ---------------- BN apply + ReLU + dropout (+ optional bf16 split) -------
__global__ void k_apply(const float* __restrict__ Y, float* __restrict__ H,
                        int keyidx, int writeSplit) {
    int t = blockIdx.x * blockDim.x + threadIdx.x;
    size_t base = (size_t)t * 4;
    if (base >= (size_t)NN * DD) return;
    uint2 key = g_keys[keyidx];
    float4 v  = *(const float4*)(Y + base);
    int col0  = (int)(base & 127);
    float4 sc = *(const float4*)(g_scale + col0);
    float4 sh = *(const float4*)(g_shift + col0);
    float vv[4]  = {v.x, v.y, v.z, v.w};
    float scv[4] = {sc.x, sc.y, sc.z, sc.w};
    float shv[4] = {sh.x, sh.y, sh.z, sh.w};
    float o[4];
#pragma unroll
    for (int j = 0; j < 4; j++) {
        float val = fmaxf(vv[j] * scv[j] + shv[j], 0.f);
        uint2 r = threefry(key.x, key.y, 0u, (uint32_t)(base + j));
        uint32_t bits = r.x ^ r.y;
        o[j] = (bits & 0x80000000u) ? 0.f : val * 2.f;
    }
    *(float4*)(H + base) = make_float4(o[0], o[1], o[2], o[3]);
    if (writeSplit) {
#pragma unroll
        for (int j = 0; j < 4; j++) {
            __nv_bfloat16 h = __float2bfloat16(o[j]);
            __nv_bfloat16 l = __float2bfloat16(o[j] - __bfloat162float(h));
            g_Hh[base + j] = h;
            g_Hl[base + j] = l;
        }
    }
}

// ---------------- layer 3: P = h@W3l, S = h@W3r + b3 -----------------------
__global__ void k_gemm3(const float* __restrict__ Hin,
                        const float* __restrict__ W3l,
                        const float* __restrict__ W3r,
                        const float* __restrict__ b3) {
    __shared__ float Ws[128 * 32];
    for (int i = threadIdx.x; i < 128 * 16; i += 256) {
        int k = i >> 4, c = i & 15;
        Ws[k * 32 + c]      = W3l[i];
        Ws[k * 32 + 16 + c] = W3r[i];
    }
    __syncthreads();
    int row = blockIdx.x * 8 + (threadIdx.x >> 5);
    int col = threadIdx.x & 31;
    if (row >= NN) return;
    const float* h = Hin + (size_t)row * DD;
    float acc = 0.f;
#pragma unroll 8
    for (int k = 0; k < 128; k += 4) {
        float4 hv = *(const float4*)(h + k);
        acc += hv.x * Ws[(k + 0) * 32 + col];
        acc += hv.y * Ws[(k + 1) * 32 + col];
        acc += hv.z * Ws[(k + 2) * 32 + col];
        acc += hv.w * Ws[(k + 3) * 32 + col];
    }
    if (col >= 16) acc += b3[col - 16];
    g_PS[(size_t)row * 32 + col] = acc;
}

__global__ void k_aggout(float* __restrict__ out) {
    int t = blockIdx.x * blockDim.x + threadIdx.x;
    int node = t >> 4, c = t & 15;
    if (node >= NN) return;
    int s0 = g_rowptr[node], s1 = g_rowptr[node + 1];
    float acc = 0.f;
    int e = s0;
    for (; e + 2 <= s1; e += 2) {
        int a = g_csrsrc[e], b = g_csrsrc[e + 1];
        acc += g_PS[(size_t)a * 32 + c] + g_PS[(size_t)b * 32 + c];
    }
    for (; e < s1; e++) acc += g_PS[(size_t)g_csrsrc[e] * 32 + c];
    out[node * 16 + c] = acc / fmaxf((float)(s1 - s0), 1.f)
                       + g_PS[(size_t)node * 32 + 16 + c];
}

// ---------------- launch ---------------------------------------------------
extern "C" void kernel_launch(void* const* d_in, const int* in_sizes, int n_in,
                              void* d_out, int out_size) {
    const float* x   = (const float*)d_in[0];
    const int*   ei  = (const int*)d_in[1];
    const int*   src = ei;
    const int*   dst = ei + EE;
    const float* W1l = (const float*)d_in[2];
    const float* W1r = (const float*)d_in[3];
    const float* b1  = (const float*)d_in[4];
    const float* g1  = (const float*)d_in[5];
    const float* be1 = (const float*)d_in[6];
    const float* W2l = (const float*)d_in[7];
    const float* W2r = (const float*)d_in[8];
    const float* b2  = (const float*)d_in[9];
    const float* g2  = (const float*)d_in[10];
    const float* be2 = (const float*)d_in[11];
    const float* W3l = (const float*)d_in[12];
    const float* W3r = (const float*)d_in[13];
    const float* b3  = (const float*)d_in[14];
    float* out = (float*)d_out;

    void *pY, *pH, *pMh, *pMl, *pXh, *pXl, *pHh, *pHl, *pWt1, *pWt2, *pCS, *pCQ;
    cudaGetSymbolAddress(&pY,  g_Y);
    cudaGetSymbolAddress(&pH,  g_H);
    cudaGetSymbolAddress(&pMh, g_Mh);
    cudaGetSymbolAddress(&pMl, g_Ml);
    cudaGetSymbolAddress(&pXh, g_Xh);
    cudaGetSymbolAddress(&pXl, g_Xl);
    cudaGetSymbolAddress(&pHh, g_Hh);
    cudaGetSymbolAddress(&pHl, g_Hl);
    cudaGetSymbolAddress(&pWt1, g_Wt1);
    cudaGetSymbolAddress(&pWt2, g_Wt2);
    cudaGetSymbolAddress(&pCS, g_colsum);
    cudaGetSymbolAddress(&pCQ, g_colsq);

    cudaFuncSetAttribute(k_mma, cudaFuncAttributeMaxDynamicSharedMemorySize,
                         SM_TOT);

    k_init<<<(NN + 255) / 256, 256>>>();
    k_cvt_w<<<384, 256>>>(W1l, W1r, (__nv_bfloat16*)pWt1);
    k_cvt_w<<<384, 256>>>(W2l, W2r, (__nv_bfloat16*)pWt2);
    k_cvt_x<<<(NN * DD / 4 + 255) / 256, 256>>>(x);
    k_deg<<<EE / 256, 256>>>(dst);
    k_scan1<<<SCAN_B, 1024>>>();
    k_scan2<<<1, 128>>>();
    k_scan3<<<SCAN_B, 1024>>>();
    k_fill<<<EE / 256, 256>>>(src, dst);

    int gemm_grid = (NN + 127) / 128;   // 782

    // layer 1
    k_agg<<<NN / 8, 256>>>(x);
    k_mma<<<gemm_grid, 512, SM_TOT>>>(
        (const __nv_bfloat16*)pMh, (const __nv_bfloat16*)pMl,
        (const __nv_bfloat16*)pXh, (const __nv_bfloat16*)pXl,
        (const __nv_bfloat16*)pWt1, b1, (float*)pY,
        (float*)pCS, (float*)pCQ);
    k_finalize<<<1, 128>>>(g1, be1, 0);
    k_apply<<<(NN * DD / 4 + 255) / 256, 256>>>((const float*)pY, (float*)pH, 0, 1);

    // layer 2
    k_agg<<<NN / 8, 256>>>((const float*)pH);
    k_mma<<<gemm_grid, 512, SM_TOT>>>(
        (const __nv_bfloat16*)pMh, (const __nv_bfloat16*)pMl,
        (const __nv_bfloat16*)pHh, (const __nv_bfloat16*)pHl,
        (const __nv_bfloat16*)pWt2, b2, (float*)pY,
        (float*)pCS + DD, (float*)pCQ + DD);
    k_finalize<<<1, 128>>>(g2, be2, 1);
    k_apply<<<(NN * DD / 4 + 255) / 256, 256>>>((const float*)pY, (float*)pH, 1, 0);

    // layer 3 (transform-then-aggregate)
    k_gemm3<<<(NN + 7) / 8, 256>>>((const float*)pH, W3l, W3r, b3);
    k_aggout<<<NN * 16 / 256, 256>>>(out);
}

// round 17
// speedup vs baseline: 1.2087x; 1.2087x over previous
#include <cuda_runtime.h>
#include <cuda_bf16.h>
#include <cuda_fp16.h>
#include <stdint.h>

#define NN 100000
#define DD 128
#define EE 1600000
#define SCAN_B 98   // ceil(NN/1024)

// ---------------- scratch (device globals: no allocation allowed) ----------
__device__ __align__(16) float g_Y[(size_t)NN*DD];   // pre-BN linear output
__device__ __align__(16) float g_PS[(size_t)NN*32];  // layer3: [P(16) | S(16)]
__device__ __align__(16) __half g_Xf[(size_t)NN*DD];         // x fp16 (gather)
__device__ __align__(16) __half g_Hf[(size_t)NN*DD];         // h fp16 (gather)
__device__ __align__(16) __nv_bfloat16 g_Mh[(size_t)NN*DD];  // mean hi
__device__ __align__(16) __nv_bfloat16 g_Ml[(size_t)NN*DD];  // mean lo
__device__ __align__(16) __nv_bfloat16 g_Xh[(size_t)NN*DD];  // x hi
__device__ __align__(16) __nv_bfloat16 g_Xl[(size_t)NN*DD];  // x lo
__device__ __align__(16) __nv_bfloat16 g_Hh[(size_t)NN*DD];  // h hi
__device__ __align__(16) __nv_bfloat16 g_Hl[(size_t)NN*DD];  // h lo
__device__ __align__(16) __nv_bfloat16 g_Wt1[128*768];       // layer1 weights, [n][k]
__device__ __align__(16) __nv_bfloat16 g_Wt2[128*768];       // layer2 weights, [n][k]
__device__ int g_deg[NN];
__device__ int g_rowptr[NN+1];
__device__ int g_cursor[NN];
__device__ int g_csrsrc[EE];
__device__ int g_bsum[SCAN_B];
__device__ int g_boff[SCAN_B];
__device__ __align__(16) float g_colsum[2][DD];
__device__ __align__(16) float g_colsq[2][DD];
__device__ __align__(16) float g_scale[DD];
__device__ __align__(16) float g_shift[DD];
__device__ uint2 g_keys[2];

// ---------------- threefry2x32 (matches JAX) ------------------------------
__device__ __forceinline__ uint32_t rotl32(uint32_t v, int d) {
    return (v << d) | (v >> (32 - d));
}

__device__ __forceinline__ uint2 threefry(uint32_t k0, uint32_t k1,
                                          uint32_t x0, uint32_t x1) {
    uint32_t k2 = k0 ^ k1 ^ 0x1BD11BDAu;
    x0 += k0; x1 += k1;
#define TFR(a,b,c,d) \
    x0+=x1; x1=rotl32(x1,a); x1^=x0; \
    x0+=x1; x1=rotl32(x1,b); x1^=x0; \
    x0+=x1; x1=rotl32(x1,c); x1^=x0; \
    x0+=x1; x1=rotl32(x1,d); x1^=x0;
    TFR(13,15,26,6)   x0+=k1; x1+=k2+1u;
    TFR(17,29,16,24)  x0+=k2; x1+=k0+2u;
    TFR(13,15,26,6)   x0+=k0; x1+=k1+3u;
    TFR(17,29,16,24)  x0+=k1; x1+=k2+4u;
    TFR(13,15,26,6)   x0+=k2; x1+=k0+5u;
#undef TFR
    return make_uint2(x0, x1);
}

// ---------------- fused init: zero deg, keys, zero both stat buffers -------
__global__ void k_init() {
    int i = blockIdx.x * blockDim.x + threadIdx.x;
    if (i < NN) g_deg[i] = 0;
    if (blockIdx.x == 0) {
        if (threadIdx.x == 0) {
            g_keys[0] = threefry(0u, 42u, 0u, 0u);
            g_keys[1] = threefry(0u, 42u, 0u, 1u);
        }
        if (threadIdx.x < 128) {
            g_colsum[0][threadIdx.x] = 0.f; g_colsq[0][threadIdx.x] = 0.f;
            g_colsum[1][threadIdx.x] = 0.f; g_colsq[1][threadIdx.x] = 0.f;
        }
    }
}

// ---------------- CSR build ------------------------------------------------
__global__ void k_deg(const int* __restrict__ dst) {
    int e = blockIdx.x * blockDim.x + threadIdx.x;
    if (e < EE) atomicAdd(&g_deg[dst[e]], 1);
}

__global__ void k_scan1() {
    __shared__ int sh[1024];
    int tid = threadIdx.x;
    int i = blockIdx.x * 1024 + tid;
    int v = (i < NN) ? g_deg[i] : 0;
    sh[tid] = v;
    __syncthreads();
    for (int off = 1; off < 1024; off <<= 1) {
        int t = (tid >= off) ? sh[tid - off] : 0;
        __syncthreads();
        sh[tid] += t;
        __syncthreads();
    }
    if (i < NN) g_rowptr[i] = sh[tid] - v;
    if (tid == 1023) g_bsum[blockIdx.x] = sh[1023];
}

__global__ void k_scan2() {
    __shared__ int sh[128];
    int tid = threadIdx.x;
    int v = (tid < SCAN_B) ? g_bsum[tid] : 0;
    sh[tid] = v;
    __syncthreads();
    for (int off = 1; off < 128; off <<= 1) {
        int t = (tid >= off) ? sh[tid - off] : 0;
        __syncthreads();
        sh[tid] += t;
        __syncthreads();
    }
    if (tid < SCAN_B) g_boff[tid] = sh[tid] - v;
    if (tid == 127) g_rowptr[NN] = sh[127];
}

__global__ void k_scan3() {
    int i = blockIdx.x * blockDim.x + threadIdx.x;
    if (i < NN) {
        int r = g_rowptr[i] + g_boff[i >> 10];
        g_rowptr[i] = r;
        g_cursor[i] = r;
    }
}

__global__ void k_fill(const int* __restrict__ src, const int* __restrict__ dst) {
    int e = blockIdx.x * blockDim.x + threadIdx.x;
    if (e < EE) {
        int p = atomicAdd(&g_cursor[dst[e]], 1);
        g_csrsrc[p] = src[e];
    }
}

// ---------------- mean aggregation (warp per node, fp16 gather) ------------
// Each lane handles 4 columns: 8B load per row. Accumulate fp32, split bf16.
__global__ void k_agg(const __half* __restrict__ Xf) {
    int w = (blockIdx.x * blockDim.x + threadIdx.x) >> 5;
    int lane = threadIdx.x & 31;
    if (w >= NN) return;
    int s0 = g_rowptr[w], s1 = g_rowptr[w + 1];
    float4 acc = make_float4(0.f, 0.f, 0.f, 0.f);
    int e = s0;
    for (; e + 4 <= s1; e += 4) {
        int a = g_csrsrc[e], b = g_csrsrc[e+1], c = g_csrsrc[e+2], d = g_csrsrc[e+3];
        uint2 ra = *(const uint2*)(Xf + (size_t)a * DD + lane * 4);
        uint2 rb = *(const uint2*)(Xf + (size_t)b * DD + lane * 4);
        uint2 rc = *(const uint2*)(Xf + (size_t)c * DD + lane * 4);
        uint2 rd = *(const uint2*)(Xf + (size_t)d * DD + lane * 4);
#pragma unroll
        for (int q = 0; q < 4; q++) {
            uint2 r = (q == 0) ? ra : (q == 1) ? rb : (q == 2) ? rc : rd;
            float2 lo = __half22float2(*(const __half2*)&r.x);
            float2 hi = __half22float2(*(const __half2*)&r.y);
            acc.x += lo.x; acc.y += lo.y; acc.z += hi.x; acc.w += hi.y;
        }
    }
    for (; e < s1; e++) {
        int a = g_csrsrc[e];
        uint2 r = *(const uint2*)(Xf + (size_t)a * DD + lane * 4);
        float2 lo = __half22float2(*(const __half2*)&r.x);
        float2 hi = __half22float2(*(const __half2*)&r.y);
        acc.x += lo.x; acc.y += lo.y; acc.z += hi.x; acc.w += hi.y;
    }
    float inv = 1.f / fmaxf((float)(s1 - s0), 1.f);
    float m[4] = {acc.x * inv, acc.y * inv, acc.z * inv, acc.w * inv};
    size_t base = (size_t)w * DD + lane * 4;
#pragma unroll
    for (int j = 0; j < 4; j++) {
        __nv_bfloat16 h = __float2bfloat16(m[j]);
        __nv_bfloat16 l = __float2bfloat16(m[j] - __bfloat162float(h));
        g_Mh[base + j] = h;
        g_Ml[base + j] = l;
    }
}

// ---------------- split x into bf16 hi/lo + fp16 copy ----------------------
__global__ void k_cvt_x(const float* __restrict__ X) {
    int t = blockIdx.x * blockDim.x + threadIdx.x;
    size_t base = (size_t)t * 4;
    if (base >= (size_t)NN * DD) return;
    float4 v = *(const float4*)(X + base);
    float m[4] = {v.x, v.y, v.z, v.w};
#pragma unroll
    for (int j = 0; j < 4; j++) {
        __nv_bfloat16 h = __float2bfloat16(m[j]);
        __nv_bfloat16 l = __float2bfloat16(m[j] - __bfloat162float(h));
        g_Xh[base + j] = h;
        g_Xl[base + j] = l;
        g_Xf[base + j] = __float2half(m[j]);
    }
}

// ---------------- build transposed split weights Wt[n][768] ----------------
// logical K rows: [Wl_h | Wl_l | Wl_h | Wr_h | Wr_l | Wr_h]
__global__ void k_cvt_w(const float* __restrict__ Wl, const float* __restrict__ Wr,
                        __nv_bfloat16* __restrict__ Wt) {
    int idx = blockIdx.x * blockDim.x + threadIdx.x;   // 0..98303
    if (idx >= 768 * 128) return;
    int n = idx & 127;
    int rr = idx >> 7;          // 0..767
    int seg = rr >> 7, kk = rr & 127;
    const float* src = (seg < 3) ? Wl : Wr;
    float w = src[kk * 128 + n];
    __nv_bfloat16 h = __float2bfloat16(w);
    __nv_bfloat16 l = __float2bfloat16(w - __bfloat162float(h));
    bool lopart = (seg == 1 || seg == 4);
    Wt[(size_t)n * 768 + rr] = lopart ? l : h;
}

// ================= helpers ================================================
__device__ __forceinline__ uint32_t s2u(const void* p) {
    uint32_t a;
    asm("{ .reg .u64 t; cvta.to.shared.u64 t, %1; cvt.u32.u64 %0, t; }"
        : "=r"(a) : "l"(p));
    return a;
}

__device__ __forceinline__ void cp_async16(uint32_t saddr, const void* gaddr, int sz) {
    asm volatile("cp.async.cg.shared.global [%0], [%1], 16, %2;"
                 :: "r"(saddr), "l"(gaddr), "r"(sz));
}

__device__ __forceinline__ void ldsm_x4(uint32_t* r, uint32_t addr) {
    asm volatile("ldmatrix.sync.aligned.m8n8.x4.shared.b16 {%0,%1,%2,%3}, [%4];"
                 : "=r"(r[0]), "=r"(r[1]), "=r"(r[2]), "=r"(r[3]) : "r"(addr));
}

// smem: 3 stages x (A 16KB + B 16KB) + aux
#define ST_BYTES 32768
#define SM_BIAS  98304
#define SM_RS    (98304 + 512)
#define SM_RQ    (98304 + 1024)
#define SM_TOT   (98304 + 1536)

// ---------------- HMMA GEMM: C[128r,128c] = A[128,768] @ Wt^T + bias -------
// 12 K-chunks of 64: A source = {Mh,Mh,Ml,Bh,Bh,Bl}[h>>1], col (h&1)*64
// round-11 config: 256 threads, 2 CTAs/SM (proven optimum)
__global__ __launch_bounds__(256, 2)
void k_mma(const __nv_bfloat16* __restrict__ Ah,
           const __nv_bfloat16* __restrict__ Al,
           const __nv_bfloat16* __restrict__ Bh,
           const __nv_bfloat16* __restrict__ Bl,
           const __nv_bfloat16* __restrict__ Wt,
           const float* __restrict__ bias,
           float* __restrict__ C,
           float* __restrict__ colsum,
           float* __restrict__ colsq) {
    extern __shared__ __align__(128) char smem[];
    uint32_t su = s2u(smem);
    int tid  = threadIdx.x;
    int lane = tid & 31;
    int warp = tid >> 5;
    int wm = warp & 1;          // 2 warps over M (64 rows)
    int wn = warp >> 1;         // 4 warps over N (32 cols)
    int row0 = blockIdx.x * 128;

    float* biasS = (float*)(smem + SM_BIAS);
    float* redS  = (float*)(smem + SM_RS);
    float* redQ  = (float*)(smem + SM_RQ);
    if (tid < 128) { biasS[tid] = bias[tid]; redS[tid] = 0.f; redQ[tid] = 0.f; }

    // issue one stage's cp.async group (A tile + B tile, 128x64 bf16 each)
    auto issue = [&](int h) {
        int c = h >> 1;
        const __nv_bfloat16* Asrc =
            (c <= 1) ? Ah : (c == 2) ? Al : (c <= 4) ? Bh : Bl;
        int acol = (h & 1) * 64;
        uint32_t sa = su + (h % 3) * ST_BYTES;
        uint32_t sb = sa + 16384;
#pragma unroll
        for (int t = 0; t < 4; t++) {
            int q = tid + t * 256;          // 0..1023
            int r = q >> 3, g = q & 7;
            uint32_t off = (uint32_t)r * 128 + (((uint32_t)g << 4) ^ ((uint32_t)(r & 7) << 4));
            bool live = (row0 + r) < NN;
            const __nv_bfloat16* gA =
                Asrc + (live ? ((size_t)(row0 + r) * 128 + acol + g * 8) : 0);
            cp_async16(sa + off, gA, live ? 16 : 0);
            const __nv_bfloat16* gB = Wt + (size_t)r * 768 + h * 64 + g * 8;
            cp_async16(sb + off, gB, 16);
        }
        asm volatile("cp.async.commit_group;" ::: "memory");
    };

    issue(0);
    issue(1);

    float acc[4][4][4];
#pragma unroll
    for (int i = 0; i < 4; i++)
#pragma unroll
        for (int j = 0; j < 4; j++)
#pragma unroll
            for (int k = 0; k < 4; k++) acc[i][j][k] = 0.f;

    int sub = lane >> 3, ri = lane & 7;
    int rsel = ((sub & 1) << 3) + ri;      // row offset within 16-row frag
    int csel = (sub >> 1) << 4;            // 0 or 16 bytes (k half)

    for (int h = 0; h < 12; h++) {
        // final iteration: only its own group pending — drain fully
        if (h == 11)
            asm volatile("cp.async.wait_group 0;" ::: "memory");
        else
            asm volatile("cp.async.wait_group 1;" ::: "memory");
        __syncthreads();
        uint32_t sa = su + (h % 3) * ST_BYTES;
        uint32_t sb = sa + 16384;
#pragma unroll
        for (int ks = 0; ks < 4; ks++) {
            int kb = ks * 32;
            uint32_t af[4][4];
#pragma unroll
            for (int mt = 0; mt < 4; mt++) {
                int r = wm * 64 + mt * 16 + rsel;
                int bc = kb + csel;
                uint32_t ad = sa + (uint32_t)r * 128
                            + ((uint32_t)bc ^ ((uint32_t)ri << 4));
                ldsm_x4(af[mt], ad);
            }
            uint32_t bfr[4][2];
#pragma unroll
            for (int p = 0; p < 2; p++) {
                int r = wn * 32 + p * 16 + rsel;
                int bc = kb + csel;
                uint32_t ad = sb + (uint32_t)r * 128
                            + ((uint32_t)bc ^ ((uint32_t)ri << 4));
                uint32_t q[4];
                ldsm_x4(q, ad);
                bfr[2*p][0]   = q[0]; bfr[2*p][1]   = q[2];
                bfr[2*p+1][0] = q[1]; bfr[2*p+1][1] = q[3];
            }
#pragma unroll
            for (int mt = 0; mt < 4; mt++)
#pragma unroll
                for (int nt = 0; nt < 4; nt++) {
                    asm volatile(
                        "mma.sync.aligned.m16n8k16.row.col.f32.bf16.bf16.f32 "
                        "{%0,%1,%2,%3}, {%4,%5,%6,%7}, {%8,%9}, {%0,%1,%2,%3};"
                        : "+f"(acc[mt][nt][0]), "+f"(acc[mt][nt][1]),
                          "+f"(acc[mt][nt][2]), "+f"(acc[mt][nt][3])
                        : "r"(af[mt][0]), "r"(af[mt][1]),
                          "r"(af[mt][2]), "r"(af[mt][3]),
                          "r"(bfr[nt][0]), "r"(bfr[nt][1]));
                }
        }
        if (h + 2 < 12) issue(h + 2);
    }

    // ---- epilogue: bias, store, fused BN stats ----
    int g4 = lane >> 2, t4 = lane & 3;
    float bias2[4][2];
#pragma unroll
    for (int nt = 0; nt < 4; nt++) {
        int nc = wn * 32 + nt * 8 + 2 * t4;
        bias2[nt][0] = biasS[nc];
        bias2[nt][1] = biasS[nc + 1];
    }
    float cs[4][2], cq[4][2];
#pragma unroll
    for (int nt = 0; nt < 4; nt++) { cs[nt][0]=0.f; cs[nt][1]=0.f; cq[nt][0]=0.f; cq[nt][1]=0.f; }
#pragma unroll
    for (int mt = 0; mt < 4; mt++) {
        int r0 = row0 + wm * 64 + mt * 16 + g4;
        int r1 = r0 + 8;
#pragma unroll
        for (int nt = 0; nt < 4; nt++) {
            int nc = wn * 32 + nt * 8 + 2 * t4;
            if (r0 < NN) {
                float v0 = acc[mt][nt][0] + bias2[nt][0];
                float v1 = acc[mt][nt][1] + bias2[nt][1];
                *(float2*)(C + (size_t)r0 * 128 + nc) = make_float2(v0, v1);
                cs[nt][0] += v0; cq[nt][0] += v0 * v0;
                cs[nt][1] += v1; cq[nt][1] += v1 * v1;
            }
            if (r1 < NN) {
                float v2 = acc[mt][nt][2] + bias2[nt][0];
                float v3 = acc[mt][nt][3] + bias2[nt][1];
                *(float2*)(C + (size_t)r1 * 128 + nc) = make_float2(v2, v3);
                cs[nt][0] += v2; cq[nt][0] += v2 * v2;
                cs[nt][1] += v3; cq[nt][1] += v3 * v3;
            }
        }
    }
    __syncthreads();
#pragma unroll
    for (int nt = 0; nt < 4; nt++) {
        int nc = wn * 32 + nt * 8 + 2 * t4;
        atomicAdd(&redS[nc],     cs[nt][0]);
        atomicAdd(&redS[nc + 1], cs[nt][1]);
        atomicAdd(&redQ[nc],     cq[nt][0]);
        atomicAdd(&redQ[nc + 1], cq[nt][1]);
    }
    __syncthreads();
    if (tid < 128) {
        atomicAdd(&colsum[tid], redS[tid]);
        atomicAdd(&colsq[tid],  redQ[tid]);
    }
}

// ---------------- BN finalize ----------------------------------------------
__global__ void k_finalize(const float* __restrict__ gamma,
                           const float* __restrict__ beta, int layer) {
    int c = threadIdx.x;
    float mu  = g_colsum[layer][c] / (float)NN;
    float var = g_colsq[layer][c] / (float)NN - mu * mu;
    float r = rsqrtf(var + 1e-5f);
    float sc = gamma[c] * r;
    g_scale[c] = sc;
    g_shift[c] = beta[c] - mu * sc;
}

// ---------------- BN apply + ReLU + dropout → fp16 (+ optional bf16 split) -
__global__ void k_apply(const float* __restrict__ Y, int keyidx, int writeSplit) {
    int t = blockIdx.x * blockDim.x + threadIdx.x;
    size_t base = (size_t)t * 4;
    if (base >= (size_t)NN * DD) return;
    uint2 key = g_keys[keyidx];
    float4 v  = *(const float4*)(Y + base);
    int col0  = (int)(base & 127);
    float4 sc = *(const float4*)(g_scale + col0);
    float4 sh = *(const float4*)(g_shift + col0);
    float vv[4]  = {v.x, v.y, v.z, v.w};
    float scv[4] = {sc.x, sc.y, sc.z, sc.w};
    float shv[4] = {sh.x, sh.y, sh.z, sh.w};
    float o[4];
#pragma unroll
    for (int j = 0; j < 4; j++) {
        float val = fmaxf(vv[j] * scv[j] + shv[j], 0.f);
        uint2 r = threefry(key.x, key.y, 0u, (uint32_t)(base + j));
        uint32_t bits = r.x ^ r.y;
        o[j] = (bits & 0x80000000u) ? 0.f : val * 2.f;
    }
#pragma unroll
    for (int j = 0; j < 4; j++) g_Hf[base + j] = __float2half(o[j]);
    if (writeSplit) {
#pragma unroll
        for (int j = 0; j < 4; j++) {
            __nv_bfloat16 h = __float2bfloat16(o[j]);
            __nv_bfloat16 l = __float2bfloat16(o[j] - __bfloat162float(h));
            g_Hh[base + j] = h;
            g_Hl[base + j] = l;
        }
    }
}

// ---------------- layer 3: P = h@W3l, S = h@W3r + b3 (fp16 h input) --------
__global__ void k_gemm3(const __half* __restrict__ Hin,
                        const float* __restrict__ W3l,
                        const float* __restrict__ W3r,
                        const float* __restrict__ b3) {
    __shared__ float Ws[128 * 32];
    for (int i = threadIdx.x; i < 128 * 16; i += 256) {
        int k = i >> 4, c = i & 15;
        Ws[k * 32 + c]      = W3l[i];
        Ws[k * 32 + 16 + c] = W3r[i];
    }
    __syncthreads();
    int row = blockIdx.x * 8 + (threadIdx.x >> 5);
    int col = threadIdx.x & 31;
    if (row >= NN) return;
    const __half* h = Hin + (size_t)row * DD;
    float acc = 0.f;
#pragma unroll 4
    for (int k = 0; k < 128; k += 8) {
        uint4 raw = *(const uint4*)(h + k);
        float2 p0 = __half22float2(*(const __half2*)&raw.x);
        float2 p1 = __half22float2(*(const __half2*)&raw.y);
        float2 p2 = __half22float2(*(const __half2*)&raw.z);
        float2 p3 = __half22float2(*(const __half2*)&raw.w);
        acc += p0.x * Ws[(k + 0) * 32 + col];
        acc += p0.y * Ws[(k + 1) * 32 + col];
        acc += p1.x * Ws[(k + 2) * 32 + col];
        acc += p1.y * Ws[(k + 3) * 32 + col];
        acc += p2.x * Ws[(k + 4) * 32 + col];
        acc += p2.y * Ws[(k + 5) * 32 + col];
        acc += p3.x * Ws[(k + 6) * 32 + col];
        acc += p3.y * Ws[(k + 7) * 32 + col];
    }
    if (col >= 16) acc += b3[col - 16];
    g_PS[(size_t)row * 32 + col] = acc;
}

__global__ void k_aggout(float* __restrict__ out) {
    int t = blockIdx.x * blockDim.x + threadIdx.x;
    int node = t >> 4, c = t & 15;
    if (node >= NN) return;
    int s0 = g_rowptr[node], s1 = g_rowptr[node + 1];
    float acc = 0.f;
    int e = s0;
    for (; e + 2 <= s1; e += 2) {
        int a = g_csrsrc[e], b = g_csrsrc[e + 1];
        acc += g_PS[(size_t)a * 32 + c] + g_PS[(size_t)b * 32 + c];
    }
    for (; e < s1; e++) acc += g_PS[(size_t)g_csrsrc[e] * 32 + c];
    out[node * 16 + c] = acc / fmaxf((float)(s1 - s0), 1.f)
                       + g_PS[(size_t)node * 32 + 16 + c];
}

// ---------------- launch ---------------------------------------------------
extern "C" void kernel_launch(void* const* d_in, const int* in_sizes, int n_in,
                              void* d_out, int out_size) {
    const float* x   = (const float*)d_in[0];
    const int*   ei  = (const int*)d_in[1];
    const int*   src = ei;
    const int*   dst = ei + EE;
    const float* W1l = (const float*)d_in[2];
    const float* W1r = (const float*)d_in[3];
    const float* b1  = (const float*)d_in[4];
    const float* g1  = (const float*)d_in[5];
    const float* be1 = (const float*)d_in[6];
    const float* W2l = (const float*)d_in[7];
    const float* W2r = (const float*)d_in[8];
    const float* b2  = (const float*)d_in[9];
    const float* g2  = (const float*)d_in[10];
    const float* be2 = (const float*)d_in[11];
    const float* W3l = (const float*)d_in[12];
    const float* W3r = (const float*)d_in[13];
    const float* b3  = (const float*)d_in[14];
    float* out = (float*)d_out;

    void *pY, *pXf, *pHf, *pMh, *pMl, *pXh, *pXl, *pHh, *pHl, *pWt1, *pWt2, *pCS, *pCQ;
    cudaGetSymbolAddress(&pY,  g_Y);
    cudaGetSymbolAddress(&pXf, g_Xf);
    cudaGetSymbolAddress(&pHf, g_Hf);
    cudaGetSymbolAddress(&pMh, g_Mh);
    cudaGetSymbolAddress(&pMl, g_Ml);
    cudaGetSymbolAddress(&pXh, g_Xh);
    cudaGetSymbolAddress(&pXl, g_Xl);
    cudaGetSymbolAddress(&pHh, g_Hh);
    cudaGetSymbolAddress(&pHl, g_Hl);
    cudaGetSymbolAddress(&pWt1, g_Wt1);
    cudaGetSymbolAddress(&pWt2, g_Wt2);
    cudaGetSymbolAddress(&pCS, g_colsum);
    cudaGetSymbolAddress(&pCQ, g_colsq);

    cudaFuncSetAttribute(k_mma, cudaFuncAttributeMaxDynamicSharedMemorySize,
                         SM_TOT);

    k_init<<<(NN + 255) / 256, 256>>>();
    k_cvt_w<<<384, 256>>>(W1l, W1r, (__nv_bfloat16*)pWt1);
    k_cvt_w<<<384, 256>>>(W2l, W2r, (__nv_bfloat16*)pWt2);
    k_cvt_x<<<(NN * DD / 4 + 255) / 256, 256>>>(x);
    k_deg<<<EE / 256, 256>>>(dst);
    k_scan1<<<SCAN_B, 1024>>>();
    k_scan2<<<1, 128>>>();
    k_scan3<<<SCAN_B, 1024>>>();
    k_fill<<<EE / 256, 256>>>(src, dst);

    int gemm_grid = (NN + 127) / 128;   // 782

    // layer 1
    k_agg<<<NN / 8, 256>>>((const __half*)pXf);
    k_mma<<<gemm_grid, 256, SM_TOT>>>(
        (const __nv_bfloat16*)pMh, (const __nv_bfloat16*)pMl,
        (const __nv_bfloat16*)pXh, (const __nv_bfloat16*)pXl,
        (const __nv_bfloat16*)pWt1, b1, (float*)pY,
        (float*)pCS, (float*)pCQ);
    k_finalize<<<1, 128>>>(g1, be1, 0);
    k_apply<<<(NN * DD / 4 + 255) / 256, 256>>>((const float*)pY, 0, 1);

    // layer 2
    k_agg<<<NN / 8, 256>>>((const __half*)pHf);
    k_mma<<<gemm_grid, 256, SM_TOT>>>(
        (const __nv_bfloat16*)pMh, (const __nv_bfloat16*)pMl,
        (const __nv_bfloat16*)pHh, (const __nv_bfloat16*)pHl,
        (const __nv_bfloat16*)pWt2, b2, (float*)pY,
        (float*)pCS + DD, (float*)pCQ + DD);
    k_finalize<<<1, 128>>>(g2, be2, 1);
    k_apply<<<(NN * DD / 4 + 255) / 256, 256>>>((const float*)pY, 1, 0);

    // layer 3 (transform-then-aggregate)
    k_gemm3<<<(NN + 7) / 8, 256>>>((const __half*)pHf, W3l, W3r, b3);
    k_aggout<<<NN * 16 / 256, 256>>>(out);
}